// round 15
// baseline (speedup 1.0000x reference)
#include <cuda_runtime.h>
#include <math.h>

#define NPTS    200000
#define NBINS   512
#define TPB     256
#define BLOCKS  ((NPTS + TPB - 1) / TPB)   // 782, one point per thread
#define WPB     8                          // warps per block
#define HPAD    576                        // padded hist row (max idx 573)
#define NCOPY   16                         // global hist copies

// Global accumulators + completion ticket. Invariant: all zero at launch
// start; the last block restores them after writing d_out (graph-replay safe).
__device__ float        g_hist[NCOPY][NBINS];
__device__ unsigned int g_ticket;

__device__ __forceinline__ float ex2f(float x) {
    float y;
    asm("ex2.approx.f32 %0, %1;" : "=f"(y) : "f"(x));
    return y;
}
__device__ __forceinline__ float ldcg(const float* p) {
    float v;
    asm volatile("ld.global.cg.f32 %0, [%1];" : "=f"(v) : "l"(p));
    return v;
}

// ---------------------------------------------------------------------------
// Branchless 64-bin sweep with intensity folded into the polynomial:
//   contribution = max(e * gg, 0),  gg = fma(rt, I*B, I*A2)
// (upper clip never fires: max pdf*h/2 ~ 0.09 for sigma >= 0.03; I >= 0.)
// Every point does exactly 64 bins [b0, b0+64); hist rows padded to 576 so
// out-of-range bins land in a discard pad. No BSSY/BSYNC in the hot loop.
// Tail minimized: 16 hist copies, finalize reads 16 coalesced rows.
// ---------------------------------------------------------------------------
__global__ void __launch_bounds__(TPB, 6) main_kernel(
        const float* __restrict__ means,
        const float* __restrict__ scan_point,
        const float* __restrict__ colours,
        const float* __restrict__ coefficients,
        const float* __restrict__ opacities,
        const float* __restrict__ scales,
        float* __restrict__ out)
{
    __shared__ float  hist[WPB][HPAD];    // 18 KB: per-warp hist + pad
    __shared__ float4 cp[TPB];            //  4 KB: compacted (k, mneg, I*B, I*A2)
    __shared__ float2 cq[TPB];            //  2 KB: compacted (rt0, b0)
    __shared__ int    s_cnt;
    __shared__ unsigned int s_last;

    const int   tid   = threadIdx.x;
    const int   w     = tid >> 5;
    const int   lane  = tid & 31;
    const float flane = 0.005f * (float)lane;

    // zero own warp's hist (incl. pad); init counter
    #pragma unroll
    for (int t = 0; t < HPAD / 32; ++t) hist[w][lane + 32 * t] = 0.0f;
    if (tid == 0) s_cnt = 0;
    __syncthreads();

    // ---- fold phase: one point per thread ----
    const int p = blockIdx.x * TPB + tid;
    float4 P = make_float4(0.f, 0.f, 0.f, 0.f);
    float  rt0 = 0.f;
    int    b0  = 0;
    bool   act = false;
    if (p < NPTS) {
        float sx = scan_point[0], sy = scan_point[1], sz = scan_point[2];
        float dx = means[3 * p + 0] - sx;
        float dy = means[3 * p + 1] - sy;
        float dz = means[3 * p + 2] - sz;
        float r0 = sqrtf(fmaf(dx, dx, fmaf(dy, dy, dz * dz)));

        float sigma = fmaxf(__expf(scales[p]), 0.005f);   // BIN_RES/2
        float sinv  = __frcp_rn(sigma);

        // sigmoid via odds: t = e^c, rc = 1/(1+t), coeff = t*rc, 1-coeff = rc
        float t  = __expf(coefficients[p]);
        float rc = __frcp_rn(1.0f + t);

        float op = opacities[p];
        float co = colours[p];
        float I  = (op * op) * (co * co);

        // pdf*(h/2) = e * (A + B*(r-r0)); fold I: gg = fma(r, I*B, I*A2)
        float A  = 0.005f * 0.3989422804014327f * (t * rc) * sinv;
        float B  = 0.005f * rc * sinv * sinv;
        float A2 = A - B * r0;

        // e = 2^(-(d*k)^2), k = sinv*sqrt(0.5*log2 e)
        float k    = 0.84932180028802f * sinv;
        float mneg = -r0 * k;
        P = make_float4(k, mneg, I * B, I * A2);

        // window start: left = clip zero-crossing r0 - A/B (exact bound),
        // capped by 3.75 sigma; A/B = 0.3989*sigma*t (odds form, no divide).
        float W   = 3.18496f / k;              // 3.75 sigma in r units
        float AoB = 0.3989422804014327f * sigma * t;
        float lo  = r0 - fminf(W, AoB);
        b0  = max(0, (int)ceilf(lo * 200.0f - 1.0f));
        act = (b0 <= 511);
        rt0 = 0.005f * (float)(b0 + 1);
    }

    // ---- block-wide compaction (warp-aggregated shared atomics) ----
    unsigned m = __ballot_sync(0xFFFFFFFFu, act);
    int base = 0;
    if (lane == 0 && m) base = atomicAdd(&s_cnt, __popc(m));
    base = __shfl_sync(0xFFFFFFFFu, base, 0);
    if (act) {
        int pos = base + __popc(m & ((1u << lane) - 1u));
        cp[pos] = P;
        cq[pos] = make_float2(rt0, __int_as_float(b0));
    }
    __syncthreads();
    const int cnt = s_cnt;

    // ---- scatter: branchless 64-bin sweep per point, I pre-folded ----
    #pragma unroll 2
    for (int j = w; j < cnt; j += WPB) {
        float2 iq = cq[j];
        float4 q  = cp[j];
        int   b   = __float_as_int(iq.y) + lane;
        float rt  = iq.x + flane;

        float u0  = fmaf(rt, q.x, q.y);
        float e0  = ex2f(u0 * -u0);
        float g0  = fmaf(rt, q.z, q.w);
        float p0  = fmaxf(e0 * g0, 0.0f);

        float rt1 = rt + 0.16f;
        float u1  = fmaf(rt1, q.x, q.y);
        float e1  = ex2f(u1 * -u1);
        float g1  = fmaf(rt1, q.z, q.w);
        float p1  = fmaxf(e1 * g1, 0.0f);

        hist[w][b]      += p0;
        hist[w][b + 32] += p1;
    }

    // ---- merge 8 warp hists -> one of 16 global copies (pad discarded) ----
    __syncthreads();
    float* __restrict__ gh = g_hist[blockIdx.x & (NCOPY - 1)];
    #pragma unroll
    for (int b = tid; b < NBINS; b += TPB) {
        float s = 0.0f;
        #pragma unroll
        for (int ww = 0; ww < WPB; ++ww) s += hist[ww][b];
        atomicAdd(&gh[b], s);
    }

    // ---- last-block finalize (no spinning: only the final arrival acts) ----
    __threadfence();
    if (tid == 0)
        s_last = atomicAdd(&g_ticket, 1u);
    __syncthreads();

    if (s_last == BLOCKS - 1) {
        __threadfence();
        // two coalesced passes (bins tid and tid+256); 16 independent row
        // reads each -> high MLP, short serial tail
        #pragma unroll
        for (int half = 0; half < NBINS / TPB; ++half) {
            int b = half * TPB + tid;
            float v = 0.0f;
            #pragma unroll
            for (int c = 0; c < NCOPY; ++c)
                v += ldcg(&g_hist[c][b]);
            #pragma unroll
            for (int c = 0; c < NCOPY; ++c)
                g_hist[c][b] = 0.0f;              // restore invariant
            float r = 0.005f * (float)(b + 1);
            out[b] = v / (r * r);
        }
        __threadfence();
        __syncthreads();
        if (tid == 0) g_ticket = 0u;              // restore invariant
    }
}

// ---------------------------------------------------------------------------
extern "C" void kernel_launch(void* const* d_in, const int* in_sizes, int n_in,
                              void* d_out, int out_size)
{
    const float* means        = (const float*)d_in[0];
    const float* scan_point   = (const float*)d_in[1];
    const float* colours      = (const float*)d_in[2];
    const float* coefficients = (const float*)d_in[3];
    const float* opacities    = (const float*)d_in[4];
    const float* scales       = (const float*)d_in[5];

    float* out = (float*)d_out;

    main_kernel<<<BLOCKS, TPB>>>(means, scan_point, colours,
                                 coefficients, opacities, scales, out);
}

// round 16
// speedup vs baseline: 1.0025x; 1.0025x over previous
#include <cuda_runtime.h>
#include <math.h>

#define NPTS    200000
#define NBINS   512
#define TPB     256
#define BLOCKS  ((NPTS + TPB - 1) / TPB)   // 782, one point per thread
#define WPB     8                          // warps per block
#define HPAD    576                        // padded hist row (max bin idx 573)
#define HPAD2   (HPAD / 2)                 // float2 entries per row
#define NCOPY   16                         // global hist copies

// Global accumulators + completion ticket. Invariant: all zero at launch
// start; the last block restores them after writing d_out (graph-replay safe).
__device__ float        g_hist[NCOPY][NBINS];
__device__ unsigned int g_ticket;

__device__ __forceinline__ float ex2f(float x) {
    float y;
    asm("ex2.approx.f32 %0, %1;" : "=f"(y) : "f"(x));
    return y;
}
__device__ __forceinline__ float ldcg(const float* p) {
    float v;
    asm volatile("ld.global.cg.f32 %0, [%1];" : "=f"(v) : "l"(p));
    return v;
}

// ---------------------------------------------------------------------------
// Branchless 64-bin sweep, paired-bin layout: lane l owns adjacent bins
// (b0+2l, b0+2l+1) with b0 forced even, so the histogram update is ONE
// LDS.64 + 2 FADD + ONE STS.64 per point (LSU issue slots halved vs the
// strided layout; smem crossbar bytes unchanged). Intensity folded into the
// polynomial: contribution = max(e * gg, 0), gg = fma(rt, I*B, I*A2);
// left clip exact via the max, upper clip provably never fires.
// ---------------------------------------------------------------------------
__global__ void __launch_bounds__(TPB, 6) main_kernel(
        const float* __restrict__ means,
        const float* __restrict__ scan_point,
        const float* __restrict__ colours,
        const float* __restrict__ coefficients,
        const float* __restrict__ opacities,
        const float* __restrict__ scales,
        float* __restrict__ out)
{
    __shared__ float2 hist2[WPB][HPAD2];  // 18 KB: per-warp hist (float2) + pad
    __shared__ float4 cp[TPB];            //  4 KB: compacted (k, mneg, I*B, I*A2)
    __shared__ float2 cq[TPB];            //  2 KB: compacted (rt0, hb0)
    __shared__ int    s_cnt;
    __shared__ unsigned int s_last;

    const int   tid    = threadIdx.x;
    const int   w      = tid >> 5;
    const int   lane   = tid & 31;
    const float flane2 = 0.01f * (float)lane;   // 2 bins per lane

    // zero all hists via float4 stores (vectorized)
    {
        float4* z = (float4*)hist2;
        const float4 zv = make_float4(0.f, 0.f, 0.f, 0.f);
        #pragma unroll
        for (int i = tid; i < WPB * HPAD / 4; i += TPB) z[i] = zv;
    }
    if (tid == 0) s_cnt = 0;
    __syncthreads();

    // ---- fold phase: one point per thread ----
    const int p = blockIdx.x * TPB + tid;
    float4 P = make_float4(0.f, 0.f, 0.f, 0.f);
    float  rt0 = 0.f;
    int    hb0 = 0;
    bool   act = false;
    if (p < NPTS) {
        float sx = scan_point[0], sy = scan_point[1], sz = scan_point[2];
        float dx = means[3 * p + 0] - sx;
        float dy = means[3 * p + 1] - sy;
        float dz = means[3 * p + 2] - sz;
        float r0 = sqrtf(fmaf(dx, dx, fmaf(dy, dy, dz * dz)));

        float sigma = fmaxf(__expf(scales[p]), 0.005f);   // BIN_RES/2
        float sinv  = __frcp_rn(sigma);

        // sigmoid via odds: t = e^c, rc = 1/(1+t), coeff = t*rc, 1-coeff = rc
        float t  = __expf(coefficients[p]);
        float rc = __frcp_rn(1.0f + t);

        float op = opacities[p];
        float co = colours[p];
        float I  = (op * op) * (co * co);

        // pdf*(h/2) = e * (A + B*(r-r0)); fold I: gg = fma(r, I*B, I*A2)
        float A  = 0.005f * 0.3989422804014327f * (t * rc) * sinv;
        float B  = 0.005f * rc * sinv * sinv;
        float A2 = A - B * r0;

        // e = 2^(-(d*k)^2), k = sinv*sqrt(0.5*log2 e)
        float k    = 0.84932180028802f * sinv;
        float mneg = -r0 * k;
        P = make_float4(k, mneg, I * B, I * A2);

        // window start: left = clip zero-crossing r0 - A/B (exact bound),
        // capped by 3.75 sigma; A/B = 0.3989*sigma*t (odds form, no divide).
        // b0 forced EVEN for the paired-bin float2 layout (extra left bin is
        // clipped to zero exactly by the max).
        float W   = 3.18496f / k;              // 3.75 sigma in r units
        float AoB = 0.3989422804014327f * sigma * t;
        float lo  = r0 - fminf(W, AoB);
        int b0 = (max(0, (int)ceilf(lo * 200.0f - 1.0f))) & ~1;
        act = (b0 <= 511);
        hb0 = b0 >> 1;                          // float2 index of first pair
        rt0 = 0.005f * (float)(b0 + 1);
    }

    // ---- block-wide compaction (warp-aggregated shared atomics) ----
    unsigned m = __ballot_sync(0xFFFFFFFFu, act);
    int base = 0;
    if (lane == 0 && m) base = atomicAdd(&s_cnt, __popc(m));
    base = __shfl_sync(0xFFFFFFFFu, base, 0);
    if (act) {
        int pos = base + __popc(m & ((1u << lane) - 1u));
        cp[pos] = P;
        cq[pos] = make_float2(rt0, __int_as_float(hb0));
    }
    __syncthreads();
    const int cnt = s_cnt;

    // ---- scatter: branchless 64-bin sweep, one LDS.64/STS.64 per point ----
    float2* __restrict__ hrow = hist2[w];
    #pragma unroll 2
    for (int j = w; j < cnt; j += WPB) {
        float2 iq = cq[j];
        float4 q  = cp[j];
        int   hb  = __float_as_int(iq.y) + lane;   // pair (2hb, 2hb+1)
        float rt  = iq.x + flane2;                 // r of even bin
        float rtb = rt + 0.005f;                   // r of odd bin

        float u0  = fmaf(rt,  q.x, q.y);
        float u1  = fmaf(rtb, q.x, q.y);
        float e0  = ex2f(u0 * -u0);
        float e1  = ex2f(u1 * -u1);
        float g0  = fmaf(rt,  q.z, q.w);
        float g1  = fmaf(rtb, q.z, q.w);
        float p0  = fmaxf(e0 * g0, 0.0f);
        float p1  = fmaxf(e1 * g1, 0.0f);

        float2 h = hrow[hb];
        h.x += p0;
        h.y += p1;
        hrow[hb] = h;
    }

    // ---- merge 8 warp hists -> one of 16 global copies (pad discarded) ----
    __syncthreads();
    float* __restrict__ gh = g_hist[blockIdx.x & (NCOPY - 1)];
    {
        // thread tid merges float2 entry tid (bins 2*tid, 2*tid+1); 256
        // threads cover all 512 bins in one pass of 8 LDS.64.
        float2 s = make_float2(0.f, 0.f);
        #pragma unroll
        for (int ww = 0; ww < WPB; ++ww) {
            float2 h = hist2[ww][tid];
            s.x += h.x;
            s.y += h.y;
        }
        atomicAdd(&gh[2 * tid],     s.x);
        atomicAdd(&gh[2 * tid + 1], s.y);
    }

    // ---- last-block finalize (no spinning: only the final arrival acts) ----
    __threadfence();
    if (tid == 0)
        s_last = atomicAdd(&g_ticket, 1u);
    __syncthreads();

    if (s_last == BLOCKS - 1) {
        __threadfence();
        // two coalesced passes; 16 independent row reads each -> high MLP
        #pragma unroll
        for (int half = 0; half < NBINS / TPB; ++half) {
            int b = half * TPB + tid;
            float v = 0.0f;
            #pragma unroll
            for (int c = 0; c < NCOPY; ++c)
                v += ldcg(&g_hist[c][b]);
            #pragma unroll
            for (int c = 0; c < NCOPY; ++c)
                g_hist[c][b] = 0.0f;              // restore invariant
            float r = 0.005f * (float)(b + 1);
            out[b] = v / (r * r);
        }
        __threadfence();
        __syncthreads();
        if (tid == 0) g_ticket = 0u;              // restore invariant
    }
}

// ---------------------------------------------------------------------------
extern "C" void kernel_launch(void* const* d_in, const int* in_sizes, int n_in,
                              void* d_out, int out_size)
{
    const float* means        = (const float*)d_in[0];
    const float* scan_point   = (const float*)d_in[1];
    const float* colours      = (const float*)d_in[2];
    const float* coefficients = (const float*)d_in[3];
    const float* opacities    = (const float*)d_in[4];
    const float* scales       = (const float*)d_in[5];

    float* out = (float*)d_out;

    main_kernel<<<BLOCKS, TPB>>>(means, scan_point, colours,
                                 coefficients, opacities, scales, out);
}

// round 17
// speedup vs baseline: 1.0488x; 1.0463x over previous
#include <cuda_runtime.h>
#include <math.h>

#define NPTS    200000
#define NBINS   512
#define TPB     256
#define BLOCKS  ((NPTS + TPB - 1) / TPB)   // 782, one point per thread
#define WPB     8                          // warps per block
#define HPAD    576                        // padded hist row (max idx 574)
#define NCOPY   16                         // global hist copies

// Global accumulators + completion ticket. Invariant: all zero at launch
// start; the last block restores them after writing d_out (graph-replay safe).
__device__ float        g_hist[NCOPY][NBINS];
__device__ unsigned int g_ticket;

__device__ __forceinline__ float ex2f(float x) {
    float y;
    asm("ex2.approx.f32 %0, %1;" : "=f"(y) : "f"(x));
    return y;
}
__device__ __forceinline__ float ldcg(const float* p) {
    float v;
    asm volatile("ld.global.cg.f32 %0, [%1];" : "=f"(v) : "l"(p));
    return v;
}

// ---------------------------------------------------------------------------
// Branchless 64-bin sweep, lane-relative parameterization:
//   u  = fma(flane,  k, u0),  g = fma(flane,  IB, g0)   (bins b0..b0+31)
//   u1 = fma(flane', k, u0),  g1= fma(flane', IB, g0)   (bins b0+32..b0+63)
// with u0 = (rt0-r0)*k, g0 = I*(A + B*(rt0-r0)) folded per point, so the
// scatter needs only ONE LDS.128 + ONE LDS.32 of point state. Contribution
// = max(e*g, 0): left clip exact, upper clip provably never fires.
// Strided hist layout keeps two independent RMW chains per point (ILP).
// ---------------------------------------------------------------------------
__global__ void __launch_bounds__(TPB, 6) main_kernel(
        const float* __restrict__ means,
        const float* __restrict__ scan_point,
        const float* __restrict__ colours,
        const float* __restrict__ coefficients,
        const float* __restrict__ opacities,
        const float* __restrict__ scales,
        float* __restrict__ out)
{
    __shared__ float  hist[WPB][HPAD];    // 18 KB: per-warp hist + pad
    __shared__ float4 cp[TPB];            //  4 KB: compacted (k, u0, IB, g0)
    __shared__ int    cb[TPB];            //  1 KB: compacted b0
    __shared__ int    s_cnt;
    __shared__ unsigned int s_last;

    const int   tid     = threadIdx.x;
    const int   w       = tid >> 5;
    const int   lane    = tid & 31;
    const float flane   = 0.005f * (float)lane;          // step-0 offset
    const float flane32 = flane + 0.16f;                 // step-1 offset

    // zero all hists via float4 stores (vectorized)
    {
        float4* z = (float4*)hist;
        const float4 zv = make_float4(0.f, 0.f, 0.f, 0.f);
        #pragma unroll
        for (int i = tid; i < WPB * HPAD / 4; i += TPB) z[i] = zv;
    }
    if (tid == 0) s_cnt = 0;
    __syncthreads();

    // ---- fold phase: one point per thread ----
    const int p = blockIdx.x * TPB + tid;
    float4 P = make_float4(0.f, 0.f, 0.f, 0.f);
    int    b0  = 0;
    bool   act = false;
    if (p < NPTS) {
        float sx = scan_point[0], sy = scan_point[1], sz = scan_point[2];
        float dx = means[3 * p + 0] - sx;
        float dy = means[3 * p + 1] - sy;
        float dz = means[3 * p + 2] - sz;
        float r0 = sqrtf(fmaf(dx, dx, fmaf(dy, dy, dz * dz)));

        float sigma = fmaxf(__expf(scales[p]), 0.005f);   // BIN_RES/2
        float sinv  = __frcp_rn(sigma);

        // sigmoid via odds: t = e^c, rc = 1/(1+t), coeff = t*rc, 1-coeff = rc
        float t  = __expf(coefficients[p]);
        float rc = __frcp_rn(1.0f + t);

        float op = opacities[p];
        float co = colours[p];
        float I  = (op * op) * (co * co);

        // pdf*(h/2) = e * (A + B*(r-r0))
        float A  = 0.005f * 0.3989422804014327f * (t * rc) * sinv;
        float B  = 0.005f * rc * sinv * sinv;

        // e = 2^(-(d*k)^2), k = sinv*sqrt(0.5*log2 e)
        float k = 0.84932180028802f * sinv;

        // window start: left = clip zero-crossing r0 - A/B (exact bound),
        // capped by 3.75 sigma; A/B = 0.3989*sigma*t (odds form, no divide).
        float W   = 3.18496f / k;              // 3.75 sigma in r units
        float AoB = 0.3989422804014327f * sigma * t;
        float lo  = r0 - fminf(W, AoB);
        b0  = max(0, (int)ceilf(lo * 200.0f - 1.0f));
        act = (b0 <= 511);

        // lane-relative fold at rt0 = 0.005*(b0+1)
        float rt0 = 0.005f * (float)(b0 + 1);
        float d0  = rt0 - r0;
        float u0  = d0 * k;
        float IB  = I * B;
        float g0  = fmaf(d0, IB, I * A);
        P = make_float4(k, u0, IB, g0);
    }

    // ---- block-wide compaction (warp-aggregated shared atomics) ----
    unsigned m = __ballot_sync(0xFFFFFFFFu, act);
    int base = 0;
    if (lane == 0 && m) base = atomicAdd(&s_cnt, __popc(m));
    base = __shfl_sync(0xFFFFFFFFu, base, 0);
    if (act) {
        int pos = base + __popc(m & ((1u << lane) - 1u));
        cp[pos] = P;
        cb[pos] = b0;
    }
    __syncthreads();
    const int cnt = s_cnt;

    // ---- scatter: branchless 64-bin sweep, two independent RMW chains ----
    #pragma unroll 4
    for (int j = w; j < cnt; j += WPB) {
        float4 q = cp[j];                       // (k, u0, IB, g0)
        int    b = cb[j] + lane;

        float u0  = fmaf(flane,   q.x, q.y);
        float e0  = ex2f(u0 * -u0);
        float g0  = fmaf(flane,   q.z, q.w);
        float p0  = fmaxf(e0 * g0, 0.0f);

        float u1  = fmaf(flane32, q.x, q.y);
        float e1  = ex2f(u1 * -u1);
        float g1  = fmaf(flane32, q.z, q.w);
        float p1  = fmaxf(e1 * g1, 0.0f);

        hist[w][b]      += p0;
        hist[w][b + 32] += p1;
    }

    // ---- merge 8 warp hists -> one of 16 global copies (pad discarded) ----
    __syncthreads();
    float* __restrict__ gh = g_hist[blockIdx.x & (NCOPY - 1)];
    {
        // thread tid merges bin pair (2*tid, 2*tid+1) via float2 reads
        float2 s = make_float2(0.f, 0.f);
        #pragma unroll
        for (int ww = 0; ww < WPB; ++ww) {
            float2 h = ((const float2*)hist[ww])[tid];
            s.x += h.x;
            s.y += h.y;
        }
        atomicAdd(&gh[2 * tid],     s.x);
        atomicAdd(&gh[2 * tid + 1], s.y);
    }

    // ---- last-block finalize (no spinning: only the final arrival acts) ----
    __threadfence();
    if (tid == 0)
        s_last = atomicAdd(&g_ticket, 1u);
    __syncthreads();

    if (s_last == BLOCKS - 1) {
        __threadfence();
        // two coalesced passes; 16 independent row reads each -> high MLP
        #pragma unroll
        for (int half = 0; half < NBINS / TPB; ++half) {
            int b = half * TPB + tid;
            float v = 0.0f;
            #pragma unroll
            for (int c = 0; c < NCOPY; ++c)
                v += ldcg(&g_hist[c][b]);
            #pragma unroll
            for (int c = 0; c < NCOPY; ++c)
                g_hist[c][b] = 0.0f;              // restore invariant
            float r = 0.005f * (float)(b + 1);
            out[b] = v / (r * r);
        }
        __threadfence();
        __syncthreads();
        if (tid == 0) g_ticket = 0u;              // restore invariant
    }
}

// ---------------------------------------------------------------------------
extern "C" void kernel_launch(void* const* d_in, const int* in_sizes, int n_in,
                              void* d_out, int out_size)
{
    const float* means        = (const float*)d_in[0];
    const float* scan_point   = (const float*)d_in[1];
    const float* colours      = (const float*)d_in[2];
    const float* coefficients = (const float*)d_in[3];
    const float* opacities    = (const float*)d_in[4];
    const float* scales       = (const float*)d_in[5];

    float* out = (float*)d_out;

    main_kernel<<<BLOCKS, TPB>>>(means, scan_point, colours,
                                 coefficients, opacities, scales, out);
}